// round 14
// baseline (speedup 1.0000x reference)
#include <cuda_runtime.h>
#include <cuda_bf16.h>
#include <math.h>
#include <stdint.h>

// Problem constants (MultiQueryAttention_56358560858478)
#define BB 2
#define TT 2048
#define DD 2048
#define HH 16
#define HD 128
#define MROWS (BB*TT)   // 4096
#define KV_TILES (MROWS/64)   // 64 tiles of 64 keys (both batches)

// ---------------- scratch (no allocation allowed) ----------------
__device__ float  g_Q [MROWS * DD];       // Q projection (B,T,D)
__device__ float  g_K [MROWS * HD];       // tf32-rounded, row-major
__device__ float  g_V [MROWS * HD];       // tf32-rounded, row-major
__device__ float4 g_Kf[KV_TILES * 2048];  // K paired-fragment tiles
__device__ float4 g_Vf[KV_TILES * 2048];  // V paired-fragment tiles
__device__ float  g_AO[MROWS * DD];       // attention output, row-major
__device__ float4 g_Xp [MROWS * DD / 4];  // x packed (A-fragment order, tf32)
__device__ float4 g_AOp[MROWS * DD / 4];  // AO packed
__device__ float4 g_WqP[DD * DD / 4];     // weights packed (paired B-fragment order)
__device__ float4 g_WkvP[2 * DD * HD / 4];// Wk|Wv packed back-to-back
__device__ float4 g_WoP[DD * DD / 4];

// ---------------- helpers ----------------
__device__ __forceinline__ float f2tf(float x) {
    uint32_t u;
    asm("cvt.rna.tf32.f32 %0, %1;" : "=r"(u) : "f"(x));
    return __uint_as_float(u);
}

__device__ __forceinline__ uint32_t s2u(const void* p) {
    uint32_t a;
    asm("{ .reg .u64 t; cvta.to.shared.u64 t, %1; cvt.u32.u64 %0, t; }" : "=r"(a) : "l"(p));
    return a;
}

__device__ __forceinline__ void mma_tf32(float* d, const uint32_t* a, const uint32_t* b) {
    asm volatile(
        "mma.sync.aligned.m16n8k8.row.col.f32.tf32.tf32.f32 "
        "{%0,%1,%2,%3}, {%4,%5,%6,%7}, {%8,%9}, {%0,%1,%2,%3};"
        : "+f"(d[0]), "+f"(d[1]), "+f"(d[2]), "+f"(d[3])
        : "r"(a[0]), "r"(a[1]), "r"(a[2]), "r"(a[3]), "r"(b[0]), "r"(b[1]));
}

// ================= operand packing =================
// A-fragment order: unchanged from R5/R11.
__global__ void pack_A(const float* __restrict__ src, float4* __restrict__ dst, int M, int K) {
    const int o = blockIdx.x * 256 + threadIdx.x;
    const int lane = o & 31;
    const int mt   = (o >> 5) & 7;
    const int ks   = (o >> 8) & 3;
    const int tile = o >> 10;
    const int KT = K >> 5;
    const int kc = tile % KT;
    const int mb = tile / KT;
    const int m = mb*128 + mt*16 + (lane >> 2);
    const int k = kc*32 + ks*8 + (lane & 3);
    const float* s = src + (size_t)m * K + k;
    float4 v;
    v.x = f2tf(s[0]);
    v.y = f2tf(s[(size_t)8 * K]);
    v.z = f2tf(s[4]);
    v.w = f2tf(s[(size_t)8 * K + 4]);
    dst[o] = v;
}

// Paired B fragments: float4 = {W[k][n], W[k+4][n], W[k][n+8], W[k+4][n+8]}
//   offset(float4) = tile*1024 + ks*256 + ng2*32 + lane
//   n = nb*128 + ng2*16 + (lane>>2);  k = kc*32 + ks*8 + (lane&3)
__global__ void pack_B2(const float* __restrict__ src, float4* __restrict__ dst, int N, int K) {
    const int o = blockIdx.x * 256 + threadIdx.x;
    const int lane = o & 31;
    const int ng2  = (o >> 5) & 7;
    const int ks   = (o >> 8) & 3;
    const int tile = o >> 10;
    const int KT = K >> 5;
    const int kc = tile % KT;
    const int nb = tile / KT;
    const int n = nb*128 + ng2*16 + (lane >> 2);
    const int k = kc*32 + ks*8 + (lane & 3);
    const float* s = src + (size_t)k * N + n;
    dst[o] = make_float4(f2tf(s[0]), f2tf(s[(size_t)4*N]),
                         f2tf(s[8]), f2tf(s[(size_t)4*N + 8]));
}

// K/V paired-fragment packing (one-off, values already tf32).
// K tile: Kf[tile][ks(16)][g(4)][lane] = {K[r][c],K[r][c+4],K[r+8][c],K[r+8][c+4]},
//         r = tile*64 + g*16 + (lane>>2), c = ks*8 + (lane&3)
// V tile: Vf[tile][ks(8)][g(8)][lane] = {V[kk][n],V[kk+4][n],V[kk][n+8],V[kk+4][n+8]},
//         kk = tile*64 + ks*8 + (lane&3), n = g*16 + (lane>>2)
__global__ void pack_kv(const float* __restrict__ Kg, const float* __restrict__ Vg,
                        float4* __restrict__ Kfp, float4* __restrict__ Vfp)
{
    const int o = blockIdx.x * 256 + threadIdx.x;      // 0 .. 2*KV_TILES*2048-1
    const int sel = o >> 17;                           // KV_TILES*2048 = 131072
    const int oo = o & 131071;
    const int lane = oo & 31;
    const int tile = oo >> 11;
    if (sel == 0) {
        const int g  = (oo >> 5) & 3;
        const int ks = (oo >> 7) & 15;
        const int r = tile*64 + g*16 + (lane >> 2);
        const int c = ks*8 + (lane & 3);
        const float* s = Kg + (size_t)r*HD + c;
        Kfp[oo] = make_float4(s[0], s[4], s[(size_t)8*HD], s[(size_t)8*HD + 4]);
    } else {
        const int g  = (oo >> 5) & 7;
        const int ks = (oo >> 8) & 7;
        const int kk = tile*64 + ks*8 + (lane & 3);
        const int n = g*16 + (lane >> 2);
        const float* s = Vg + (size_t)kk*HD + n;
        Vfp[oo] = make_float4(s[0], s[(size_t)4*HD], s[8], s[(size_t)4*HD + 8]);
    }
}

// ================= mma.sync GEMM body (B2 paired loads) =================
#define G_STAGE_F 8192
#define G_SMEM (3 * G_STAGE_F * 4)

template<bool ROUND>
__device__ __forceinline__
void gemm_body(const float4* At, const float4* Bt, const float* bias,
               float* C, int N, int KT, int mb, int ncol0, float* sm)
{
    const int tid = threadIdx.x, lane = tid & 31, wid = tid >> 5;
    const int grp = lane >> 2, t4 = lane & 3;
    const int NC = KT;

    float acc[2][8][4];
    #pragma unroll
    for (int i = 0; i < 2; i++)
        #pragma unroll
        for (int j = 0; j < 8; j++)
            #pragma unroll
            for (int e = 0; e < 4; e++) acc[i][j][e] = 0.f;

    auto fill = [&](int ch) {
        const int s = ch % 3;
        const uint32_t da = s2u(sm + s * G_STAGE_F);
        const float4* a = At + (size_t)ch * 1024;
        const float4* b = Bt + (size_t)ch * 1024;
        #pragma unroll
        for (int i = tid; i < 1024; i += 256)
            asm volatile("cp.async.cg.shared.global [%0], [%1], 16;"
                         :: "r"(da + i*16), "l"(a + i));
        const uint32_t db = da + 4096*4;
        #pragma unroll
        for (int i = tid; i < 1024; i += 256)
            asm volatile("cp.async.cg.shared.global [%0], [%1], 16;"
                         :: "r"(db + i*16), "l"(b + i));
        asm volatile("cp.async.commit_group;" ::: "memory");
    };

    fill(0);
    if (NC > 1) fill(1);

    const int mtb  = (wid & 3) * 2;     // warp's first 16-row tile
    const int ngb2 = (wid >> 2) * 4;    // warp's first paired-n group (16 cols each)

    for (int i = 0; i < NC; i++) {
        if (i + 2 < NC) asm volatile("cp.async.wait_group 1;" ::: "memory");
        else            asm volatile("cp.async.wait_group 0;" ::: "memory");
        __syncthreads();
        if (i + 2 < NC) fill(i + 2);

        const float* sa = sm + (i % 3) * G_STAGE_F;
        const float* sb = sa + 4096;
        #pragma unroll
        for (int ks = 0; ks < 4; ks++) {
            float4 a0 = *(const float4*)&sa[ks*1024 + (mtb + 0)*128 + lane*4];
            float4 a1 = *(const float4*)&sa[ks*1024 + (mtb + 1)*128 + lane*4];
            #pragma unroll
            for (int g = 0; g < 4; g++) {
                float4 b4 = *(const float4*)&sb[ks*1024 + (ngb2 + g)*128 + lane*4];
                mma_tf32(acc[0][2*g  ], (const uint32_t*)&a0, (const uint32_t*)&b4.x);
                mma_tf32(acc[0][2*g+1], (const uint32_t*)&a0, (const uint32_t*)&b4.z);
                mma_tf32(acc[1][2*g  ], (const uint32_t*)&a1, (const uint32_t*)&b4.x);
                mma_tf32(acc[1][2*g+1], (const uint32_t*)&a1, (const uint32_t*)&b4.z);
            }
        }
        __syncthreads();
    }

    #pragma unroll
    for (int mt2 = 0; mt2 < 2; mt2++) {
        const int r = mb*128 + (wid & 3)*32 + mt2*16 + grp;
        #pragma unroll
        for (int nt = 0; nt < 8; nt++) {
            const int c = ncol0 + (wid >> 2)*64 + nt*8 + 2*t4;
            const float bz0 = bias[c], bz1 = bias[c+1];
            float v00 = acc[mt2][nt][0] + bz0, v01 = acc[mt2][nt][1] + bz1;
            float v10 = acc[mt2][nt][2] + bz0, v11 = acc[mt2][nt][3] + bz1;
            if (ROUND) { v00 = f2tf(v00); v01 = f2tf(v01); v10 = f2tf(v10); v11 = f2tf(v11); }
            *(float2*)&C[(size_t)r*N + c]     = make_float2(v00, v01);
            *(float2*)&C[(size_t)(r+8)*N + c] = make_float2(v10, v11);
        }
    }
}

__global__ __launch_bounds__(256)
void gemm_mma(const float4* __restrict__ Ap, const float4* __restrict__ Bp,
              const float* __restrict__ bias, float* __restrict__ C,
              int M, int N, int K)
{
    extern __shared__ float sm[];
    const int KT = K >> 5;
    gemm_body<false>(Ap + (size_t)blockIdx.y * KT * 1024,
                     Bp + (size_t)blockIdx.x * KT * 1024,
                     bias, C, N, KT, blockIdx.y, blockIdx.x * 128, sm);
}

__global__ __launch_bounds__(256)
void gemm_kv(const float4* __restrict__ Ap, const float4* __restrict__ Bkv,
             const float* __restrict__ bk, const float* __restrict__ bv,
             float* __restrict__ Kout, float* __restrict__ Vout, int K)
{
    extern __shared__ float sm[];
    const int KT = K >> 5;
    const int sel = blockIdx.x;
    gemm_body<true>(Ap + (size_t)blockIdx.y * KT * 1024,
                    Bkv + (size_t)sel * KT * 1024,
                    sel ? bv : bk, sel ? Vout : Kout,
                    HD, KT, blockIdx.y, 0, sm);
}

// ---------------- flash attention: paired K/V tiles, cp.async double-buffer ----
// Stage = [Kf 2048 float4][Vf 2048 float4] = 64KB. 2 stages + Pw.
#define FB_R 128
#define PS_ST 68
#define F_STAGE_F4 4096                             // float4 per stage
#define PW_OFF (2*F_STAGE_F4*4)                     // float offset of Pw region
#define FLASH_SMEM ((PW_OFF + 8*16*PS_ST) * 4)      // 165888 B

__global__ __launch_bounds__(256)
void flash_tf32(const float* __restrict__ Q,
                const float4* __restrict__ Kfp, const float4* __restrict__ Vfp,
                float* __restrict__ O)
{
    extern __shared__ float sm[];
    const uint32_t sb = s2u(sm);

    const int tid  = threadIdx.x;
    const int lane = tid & 31;
    const int wid  = tid >> 5;
    const int grp  = lane >> 2;
    const int t4   = lane & 3;
    float* Pw = sm + PW_OFF + wid*16*PS_ST;

    const int qb = gridDim.x - 1 - blockIdx.x;   // longest blocks first
    const int h  = blockIdx.y;
    const int b  = blockIdx.z;
    const int q0 = qb * FB_R;
    const int qr = q0 + wid*16 + grp;

    const float scale = 0.08838834764831845f;

    // Q fragments (scaled + rounded) in registers
    const float* Qb = Q + (size_t)b*TT*DD + (size_t)h*HD;
    uint32_t qf[16][4];
    #pragma unroll
    for (int ks = 0; ks < 16; ks++) {
        const float* p0 = &Qb[(size_t)qr*DD + ks*8 + t4];
        qf[ks][0] = __float_as_uint(f2tf(p0[0]        * scale));
        qf[ks][1] = __float_as_uint(f2tf(p0[8*DD]     * scale));
        qf[ks][2] = __float_as_uint(f2tf(p0[4]        * scale));
        qf[ks][3] = __float_as_uint(f2tf(p0[8*DD + 4] * scale));
    }

    float of[16][4];
    #pragma unroll
    for (int nt = 0; nt < 16; nt++)
        #pragma unroll
        for (int e = 0; e < 4; e++) of[nt][e] = 0.f;

    float m_lo = -1e30f, m_hi = -1e30f, l_lo = 0.f, l_hi = 0.f;

    const float4* Kt = Kfp + (size_t)b*(TT/64)*2048;  // per-batch tiles
    const float4* Vt = Vfp + (size_t)b*(TT/64)*2048;
    const int nkt = 2*(qb + 1);

    auto fill = [&](int t) {
        const uint32_t dst = sb + (uint32_t)(t & 1) * 65536;
        const float4* sk = Kt + (size_t)t * 2048;
        const float4* sv = Vt + (size_t)t * 2048;
        #pragma unroll
        for (int i = 0; i < 8; i++) {
            const int idx = tid + i*256;
            asm volatile("cp.async.cg.shared.global [%0], [%1], 16;"
                         :: "r"(dst + idx*16), "l"(sk + idx));
            asm volatile("cp.async.cg.shared.global [%0], [%1], 16;"
                         :: "r"(dst + 32768 + idx*16), "l"(sv + idx));
        }
        asm volatile("cp.async.commit_group;" ::: "memory");
    };

    fill(0);
    for (int kt = 0; kt < nkt; kt++) {
        if (kt + 1 < nkt) { fill(kt + 1); asm volatile("cp.async.wait_group 1;" ::: "memory"); }
        else              { asm volatile("cp.async.wait_group 0;" ::: "memory"); }
        __syncthreads();

        const float4* Kf = (const float4*)sm + (size_t)(kt & 1) * F_STAGE_F4;
        const float4* Vf = Kf + 2048;
        const int k0 = kt * 64;

        // ---- S = Q @ K^T (paired B fragments: 1 LDS.128 -> 2 mma) ----
        float sacc[8][4];
        #pragma unroll
        for (int nt = 0; nt < 8; nt++)
            #pragma unroll
            for (int e = 0; e < 4; e++) sacc[nt][e] = 0.f;

        #pragma unroll
        for (int ks = 0; ks < 16; ks++) {
            #pragma unroll
            for (int g = 0; g < 4; g++) {
                float4 b4 = Kf[ks*128 + g*32 + lane];
                mma_tf32(sacc[2*g  ], qf[ks], (const uint32_t*)&b4.x);
                mma_tf32(sacc[2*g+1], qf[ks], (const uint32_t*)&b4.z);
            }
        }

        // ---- causal mask (only last two tiles overlap the diagonal) ----
        if (kt >= nkt - 2) {
            #pragma unroll
            for (int nt = 0; nt < 8; nt++) {
                int kc = k0 + nt*8 + 2*t4;
                if (kc     > qr)     sacc[nt][0] = -1e30f;
                if (kc + 1 > qr)     sacc[nt][1] = -1e30f;
                if (kc     > qr + 8) sacc[nt][2] = -1e30f;
                if (kc + 1 > qr + 8) sacc[nt][3] = -1e30f;
            }
        }

        // ---- online softmax ----
        float mx_lo = -1e30f, mx_hi = -1e30f;
        #pragma unroll
        for (int nt = 0; nt < 8; nt++) {
            mx_lo = fmaxf(mx_lo, fmaxf(sacc[nt][0], sacc[nt][1]));
            mx_hi = fmaxf(mx_hi, fmaxf(sacc[nt][2], sacc[nt][3]));
        }
        mx_lo = fmaxf(mx_lo, __shfl_xor_sync(0xffffffffu, mx_lo, 1));
        mx_lo = fmaxf(mx_lo, __shfl_xor_sync(0xffffffffu, mx_lo, 2));
        mx_hi = fmaxf(mx_hi, __shfl_xor_sync(0xffffffffu, mx_hi, 1));
        mx_hi = fmaxf(mx_hi, __shfl_xor_sync(0xffffffffu, mx_hi, 2));

        const float mn_lo = fmaxf(m_lo, mx_lo);
        const float mn_hi = fmaxf(m_hi, mx_hi);
        const float corr_lo = __expf(m_lo - mn_lo);
        const float corr_hi = __expf(m_hi - mn_hi);

        float sum_lo = 0.f, sum_hi = 0.f;
        #pragma unroll
        for (int nt = 0; nt < 8; nt++) {
            sacc[nt][0] = __expf(sacc[nt][0] - mn_lo);
            sacc[nt][1] = __expf(sacc[nt][1] - mn_lo);
            sacc[nt][2] = __expf(sacc[nt][2] - mn_hi);
            sacc[nt][3] = __expf(sacc[nt][3] - mn_hi);
            sum_lo += sacc[nt][0] + sacc[nt][1];
            sum_hi += sacc[nt][2] + sacc[nt][3];
        }
        sum_lo += __shfl_xor_sync(0xffffffffu, sum_lo, 1);
        sum_lo += __shfl_xor_sync(0xffffffffu, sum_lo, 2);
        sum_hi += __shfl_xor_sync(0xffffffffu, sum_hi, 1);
        sum_hi += __shfl_xor_sync(0xffffffffu, sum_hi, 2);

        l_lo = l_lo * corr_lo + sum_lo;  m_lo = mn_lo;
        l_hi = l_hi * corr_hi + sum_hi;  m_hi = mn_hi;

        #pragma unroll
        for (int nt = 0; nt < 16; nt++) {
            of[nt][0] *= corr_lo;  of[nt][1] *= corr_lo;
            of[nt][2] *= corr_hi;  of[nt][3] *= corr_hi;
        }

        // ---- P through per-warp smem (C-layout -> A-layout), tf32 ----
        #pragma unroll
        for (int nt = 0; nt < 8; nt++) {
            float2 p01 = make_float2(f2tf(sacc[nt][0]), f2tf(sacc[nt][1]));
            *(float2*)&Pw[grp*PS_ST + nt*8 + 2*t4] = p01;
            float2 p23 = make_float2(f2tf(sacc[nt][2]), f2tf(sacc[nt][3]));
            *(float2*)&Pw[(grp + 8)*PS_ST + nt*8 + 2*t4] = p23;
        }
        __syncwarp();

        // ---- O += P @ V (paired B fragments) ----
        #pragma unroll
        for (int ks = 0; ks < 8; ks++) {
            uint32_t pf[4];
            const float* pb = &Pw[grp*PS_ST + ks*8 + t4];
            pf[0] = __float_as_uint(pb[0]);
            pf[1] = __float_as_uint(pb[8*PS_ST]);
            pf[2] = __float_as_uint(pb[4]);
            pf[3] = __float_as_uint(pb[8*PS_ST + 4]);
            #pragma unroll
            for (int g = 0; g < 8; g++) {
                float4 b4 = Vf[ks*256 + g*32 + lane];
                mma_tf32(of[2*g  ], pf, (const uint32_t*)&b4.x);
                mma_tf32(of[2*g+1], pf, (const uint32_t*)&b4.z);
            }
        }
        __syncthreads();   // stage reads done before next fill overwrites
    }

    // normalize, round to tf32 (feeds packed O-proj GEMM), write
    const float inv_lo = 1.f / l_lo;
    const float inv_hi = 1.f / l_hi;
    float* Ob = O + (size_t)b*TT*DD + (size_t)h*HD;
    #pragma unroll
    for (int nt = 0; nt < 16; nt++) {
        const int c = nt*8 + 2*t4;
        float2 v0 = make_float2(f2tf(of[nt][0]*inv_lo), f2tf(of[nt][1]*inv_lo));
        *(float2*)&Ob[(size_t)qr*DD + c] = v0;
        float2 v1 = make_float2(f2tf(of[nt][2]*inv_hi), f2tf(of[nt][3]*inv_hi));
        *(float2*)&Ob[(size_t)(qr + 8)*DD + c] = v1;
    }
}

// ---------------- launch ----------------
extern "C" void kernel_launch(void* const* d_in, const int* in_sizes, int n_in,
                              void* d_out, int out_size)
{
    const float* x  = (const float*)d_in[0];
    const float* Wq = (const float*)d_in[1];
    const float* bq = (const float*)d_in[2];
    const float* Wk = (const float*)d_in[3];
    const float* bk = (const float*)d_in[4];
    const float* Wv = (const float*)d_in[5];
    const float* bv = (const float*)d_in[6];
    const float* Wo = (const float*)d_in[7];
    const float* bo = (const float*)d_in[8];
    float* out = (float*)d_out;

    float *Qp, *Kp, *Vp, *AOr;
    float4 *Kfp, *Vfp;
    float4 *Xp, *AOp, *WqP, *WkvP, *WoP;
    cudaGetSymbolAddress((void**)&Qp,   g_Q);
    cudaGetSymbolAddress((void**)&Kp,   g_K);
    cudaGetSymbolAddress((void**)&Vp,   g_V);
    cudaGetSymbolAddress((void**)&Kfp,  g_Kf);
    cudaGetSymbolAddress((void**)&Vfp,  g_Vf);
    cudaGetSymbolAddress((void**)&AOr,  g_AO);
    cudaGetSymbolAddress((void**)&Xp,   g_Xp);
    cudaGetSymbolAddress((void**)&AOp,  g_AOp);
    cudaGetSymbolAddress((void**)&WqP,  g_WqP);
    cudaGetSymbolAddress((void**)&WkvP, g_WkvP);
    cudaGetSymbolAddress((void**)&WoP,  g_WoP);

    cudaFuncSetAttribute(gemm_mma,  cudaFuncAttributeMaxDynamicSharedMemorySize, G_SMEM);
    cudaFuncSetAttribute(gemm_kv,   cudaFuncAttributeMaxDynamicSharedMemorySize, G_SMEM);
    cudaFuncSetAttribute(flash_tf32, cudaFuncAttributeMaxDynamicSharedMemorySize, FLASH_SMEM);

    // ---- pack GEMM operands (tf32-rounded, fragment order) ----
    pack_A <<<MROWS*DD/4/256, 256>>>(x,  Xp,  MROWS, DD);
    pack_B2<<<DD*DD/4/256,    256>>>(Wq, WqP, DD, DD);
    pack_B2<<<DD*HD/4/256,    256>>>(Wk, WkvP, HD, DD);
    pack_B2<<<DD*HD/4/256,    256>>>(Wv, WkvP + DD*HD/4, HD, DD);
    pack_B2<<<DD*DD/4/256,    256>>>(Wo, WoP, DD, DD);

    // ---- projections ----
    gemm_mma<<<dim3(DD/128, MROWS/128), 256, G_SMEM>>>(Xp, WqP, bq, Qp, MROWS, DD, DD);
    gemm_kv <<<dim3(2,      MROWS/128), 256, G_SMEM>>>(Xp, WkvP, bk, bv, Kp, Vp, DD);

    // ---- pack K/V into paired-fragment tiles ----
    pack_kv<<<2*KV_TILES*2048/256, 256>>>(Kp, Vp, Kfp, Vfp);

    // ---- attention ----
    flash_tf32<<<dim3(TT/FB_R, HH, BB), 256, FLASH_SMEM>>>(Qp, Kfp, Vfp, AOr);

    // ---- output projection ----
    pack_A<<<MROWS*DD/4/256, 256>>>(AOr, AOp, MROWS, DD);
    gemm_mma<<<dim3(DD/128, MROWS/128), 256, G_SMEM>>>(AOp, WoP, bo, out, MROWS, DD, DD);
}

// round 15
// speedup vs baseline: 1.0128x; 1.0128x over previous
#include <cuda_runtime.h>
#include <cuda_bf16.h>
#include <math.h>
#include <stdint.h>

// Problem constants (MultiQueryAttention_56358560858478)
#define BB 2
#define TT 2048
#define DD 2048
#define HH 16
#define HD 128
#define MROWS (BB*TT)   // 4096
#define KV_TILES (MROWS/64)   // 64 tiles of 64 keys (both batches)

// ---------------- scratch (no allocation allowed) ----------------
__device__ float  g_Q [MROWS * DD];       // Q projection (B,T,D)
__device__ float  g_K [MROWS * HD];       // tf32-rounded, row-major
__device__ float  g_V [MROWS * HD];       // tf32-rounded, row-major
__device__ float4 g_Kf[KV_TILES * 2048];  // K paired-fragment tiles
__device__ float4 g_Vf[KV_TILES * 2048];  // V paired-fragment tiles
__device__ float4 g_Xp [MROWS * DD / 4];  // x packed (A-fragment order, tf32)
__device__ float4 g_AOp[MROWS * DD / 4];  // AO packed (written directly by flash)
__device__ float4 g_WqP[DD * DD / 4];     // weights packed (paired B-fragment order)
__device__ float4 g_WkvP[2 * DD * HD / 4];// Wk|Wv packed back-to-back
__device__ float4 g_WoP[DD * DD / 4];

// ---------------- helpers ----------------
__device__ __forceinline__ float f2tf(float x) {
    uint32_t u;
    asm("cvt.rna.tf32.f32 %0, %1;" : "=r"(u) : "f"(x));
    return __uint_as_float(u);
}

__device__ __forceinline__ uint32_t s2u(const void* p) {
    uint32_t a;
    asm("{ .reg .u64 t; cvta.to.shared.u64 t, %1; cvt.u32.u64 %0, t; }" : "=r"(a) : "l"(p));
    return a;
}

__device__ __forceinline__ void mma_tf32(float* d, const uint32_t* a, const uint32_t* b) {
    asm volatile(
        "mma.sync.aligned.m16n8k8.row.col.f32.tf32.tf32.f32 "
        "{%0,%1,%2,%3}, {%4,%5,%6,%7}, {%8,%9}, {%0,%1,%2,%3};"
        : "+f"(d[0]), "+f"(d[1]), "+f"(d[2]), "+f"(d[3])
        : "r"(a[0]), "r"(a[1]), "r"(a[2]), "r"(a[3]), "r"(b[0]), "r"(b[1]));
}

// ================= operand packing =================
// A-fragment order (reference layout; flash epilogue writes this directly for AO):
//   float4 slot = tile*1024 + ks*256 + mt*32 + lane, tile = mb*KT + kc
//   regs = {(m,k), (m+8,k), (m,k+4), (m+8,k+4)}, m = mb*128+mt*16+(lane>>2),
//   k = kc*32 + ks*8 + (lane&3)
__global__ void pack_A(const float* __restrict__ src, float4* __restrict__ dst, int M, int K) {
    const int o = blockIdx.x * 256 + threadIdx.x;
    const int lane = o & 31;
    const int mt   = (o >> 5) & 7;
    const int ks   = (o >> 8) & 3;
    const int tile = o >> 10;
    const int KT = K >> 5;
    const int kc = tile % KT;
    const int mb = tile / KT;
    const int m = mb*128 + mt*16 + (lane >> 2);
    const int k = kc*32 + ks*8 + (lane & 3);
    const float* s = src + (size_t)m * K + k;
    float4 v;
    v.x = f2tf(s[0]);
    v.y = f2tf(s[(size_t)8 * K]);
    v.z = f2tf(s[4]);
    v.w = f2tf(s[(size_t)8 * K + 4]);
    dst[o] = v;
}

// Paired B fragments: float4 = {W[k][n], W[k+4][n], W[k][n+8], W[k+4][n+8]}
__global__ void pack_B2(const float* __restrict__ src, float4* __restrict__ dst, int N, int K) {
    const int o = blockIdx.x * 256 + threadIdx.x;
    const int lane = o & 31;
    const int ng2  = (o >> 5) & 7;
    const int ks   = (o >> 8) & 3;
    const int tile = o >> 10;
    const int KT = K >> 5;
    const int kc = tile % KT;
    const int nb = tile / KT;
    const int n = nb*128 + ng2*16 + (lane >> 2);
    const int k = kc*32 + ks*8 + (lane & 3);
    const float* s = src + (size_t)k * N + n;
    dst[o] = make_float4(f2tf(s[0]), f2tf(s[(size_t)4*N]),
                         f2tf(s[8]), f2tf(s[(size_t)4*N + 8]));
}

// K/V paired-fragment packing (one-off, values already tf32).
__global__ void pack_kv(const float* __restrict__ Kg, const float* __restrict__ Vg,
                        float4* __restrict__ Kfp, float4* __restrict__ Vfp)
{
    const int o = blockIdx.x * 256 + threadIdx.x;      // 0 .. 2*KV_TILES*2048-1
    const int sel = o >> 17;                           // KV_TILES*2048 = 131072
    const int oo = o & 131071;
    const int lane = oo & 31;
    const int tile = oo >> 11;
    if (sel == 0) {
        const int g  = (oo >> 5) & 3;
        const int ks = (oo >> 7) & 15;
        const int r = tile*64 + g*16 + (lane >> 2);
        const int c = ks*8 + (lane & 3);
        const float* s = Kg + (size_t)r*HD + c;
        Kfp[oo] = make_float4(s[0], s[4], s[(size_t)8*HD], s[(size_t)8*HD + 4]);
    } else {
        const int g  = (oo >> 5) & 7;
        const int ks = (oo >> 8) & 7;
        const int kk = tile*64 + ks*8 + (lane & 3);
        const int n = g*16 + (lane >> 2);
        const float* s = Vg + (size_t)kk*HD + n;
        Vfp[oo] = make_float4(s[0], s[(size_t)4*HD], s[8], s[(size_t)4*HD + 8]);
    }
}

// ================= mma.sync GEMM body (B2 paired loads) =================
#define G_STAGE_F 8192
#define G_SMEM (3 * G_STAGE_F * 4)

template<bool ROUND>
__device__ __forceinline__
void gemm_body(const float4* At, const float4* Bt, const float* bias,
               float* C, int N, int KT, int mb, int ncol0, float* sm)
{
    const int tid = threadIdx.x, lane = tid & 31, wid = tid >> 5;
    const int grp = lane >> 2, t4 = lane & 3;
    const int NC = KT;

    float acc[2][8][4];
    #pragma unroll
    for (int i = 0; i < 2; i++)
        #pragma unroll
        for (int j = 0; j < 8; j++)
            #pragma unroll
            for (int e = 0; e < 4; e++) acc[i][j][e] = 0.f;

    auto fill = [&](int ch) {
        const int s = ch % 3;
        const uint32_t da = s2u(sm + s * G_STAGE_F);
        const float4* a = At + (size_t)ch * 1024;
        const float4* b = Bt + (size_t)ch * 1024;
        #pragma unroll
        for (int i = tid; i < 1024; i += 256)
            asm volatile("cp.async.cg.shared.global [%0], [%1], 16;"
                         :: "r"(da + i*16), "l"(a + i));
        const uint32_t db = da + 4096*4;
        #pragma unroll
        for (int i = tid; i < 1024; i += 256)
            asm volatile("cp.async.cg.shared.global [%0], [%1], 16;"
                         :: "r"(db + i*16), "l"(b + i));
        asm volatile("cp.async.commit_group;" ::: "memory");
    };

    fill(0);
    if (NC > 1) fill(1);

    const int mtb  = (wid & 3) * 2;     // warp's first 16-row tile
    const int ngb2 = (wid >> 2) * 4;    // warp's first paired-n group (16 cols each)

    for (int i = 0; i < NC; i++) {
        if (i + 2 < NC) asm volatile("cp.async.wait_group 1;" ::: "memory");
        else            asm volatile("cp.async.wait_group 0;" ::: "memory");
        __syncthreads();
        if (i + 2 < NC) fill(i + 2);

        const float* sa = sm + (i % 3) * G_STAGE_F;
        const float* sb = sa + 4096;
        #pragma unroll
        for (int ks = 0; ks < 4; ks++) {
            float4 a0 = *(const float4*)&sa[ks*1024 + (mtb + 0)*128 + lane*4];
            float4 a1 = *(const float4*)&sa[ks*1024 + (mtb + 1)*128 + lane*4];
            #pragma unroll
            for (int g = 0; g < 4; g++) {
                float4 b4 = *(const float4*)&sb[ks*1024 + (ngb2 + g)*128 + lane*4];
                mma_tf32(acc[0][2*g  ], (const uint32_t*)&a0, (const uint32_t*)&b4.x);
                mma_tf32(acc[0][2*g+1], (const uint32_t*)&a0, (const uint32_t*)&b4.z);
                mma_tf32(acc[1][2*g  ], (const uint32_t*)&a1, (const uint32_t*)&b4.x);
                mma_tf32(acc[1][2*g+1], (const uint32_t*)&a1, (const uint32_t*)&b4.z);
            }
        }
        __syncthreads();
    }

    #pragma unroll
    for (int mt2 = 0; mt2 < 2; mt2++) {
        const int r = mb*128 + (wid & 3)*32 + mt2*16 + grp;
        #pragma unroll
        for (int nt = 0; nt < 8; nt++) {
            const int c = ncol0 + (wid >> 2)*64 + nt*8 + 2*t4;
            const float bz0 = bias[c], bz1 = bias[c+1];
            float v00 = acc[mt2][nt][0] + bz0, v01 = acc[mt2][nt][1] + bz1;
            float v10 = acc[mt2][nt][2] + bz0, v11 = acc[mt2][nt][3] + bz1;
            if (ROUND) { v00 = f2tf(v00); v01 = f2tf(v01); v10 = f2tf(v10); v11 = f2tf(v11); }
            *(float2*)&C[(size_t)r*N + c]     = make_float2(v00, v01);
            *(float2*)&C[(size_t)(r+8)*N + c] = make_float2(v10, v11);
        }
    }
}

__global__ __launch_bounds__(256)
void gemm_mma(const float4* __restrict__ Ap, const float4* __restrict__ Bp,
              const float* __restrict__ bias, float* __restrict__ C,
              int M, int N, int K)
{
    extern __shared__ float sm[];
    const int KT = K >> 5;
    gemm_body<false>(Ap + (size_t)blockIdx.y * KT * 1024,
                     Bp + (size_t)blockIdx.x * KT * 1024,
                     bias, C, N, KT, blockIdx.y, blockIdx.x * 128, sm);
}

__global__ __launch_bounds__(256)
void gemm_kv(const float4* __restrict__ Ap, const float4* __restrict__ Bkv,
             const float* __restrict__ bk, const float* __restrict__ bv,
             float* __restrict__ Kout, float* __restrict__ Vout, int K)
{
    extern __shared__ float sm[];
    const int KT = K >> 5;
    const int sel = blockIdx.x;
    gemm_body<true>(Ap + (size_t)blockIdx.y * KT * 1024,
                    Bkv + (size_t)sel * KT * 1024,
                    sel ? bv : bk, sel ? Vout : Kout,
                    HD, KT, blockIdx.y, 0, sm);
}

// ---------------- flash attention: paired K/V tiles, packed-AO epilogue ----
// Stage = [Kf 2048 float4][Vf 2048 float4] = 64KB. 2 stages + Pw.
#define FB_R 128
#define PS_ST 68
#define F_STAGE_F4 4096                             // float4 per stage
#define PW_OFF (2*F_STAGE_F4*4)                     // float offset of Pw region
#define FLASH_SMEM ((PW_OFF + 8*16*PS_ST) * 4)      // 165888 B

__global__ __launch_bounds__(256)
void flash_tf32(const float* __restrict__ Q,
                const float4* __restrict__ Kfp, const float4* __restrict__ Vfp,
                float* __restrict__ AOp)        // packed A-fragment output
{
    extern __shared__ float sm[];
    const uint32_t sb = s2u(sm);

    const int tid  = threadIdx.x;
    const int lane = tid & 31;
    const int wid  = tid >> 5;
    const int grp  = lane >> 2;
    const int t4   = lane & 3;
    float* Pw = sm + PW_OFF + wid*16*PS_ST;

    const int qb = gridDim.x - 1 - blockIdx.x;   // longest blocks first
    const int h  = blockIdx.y;
    const int b  = blockIdx.z;
    const int q0 = qb * FB_R;
    const int qr = q0 + wid*16 + grp;

    const float scale = 0.08838834764831845f;

    // Q fragments (scaled + rounded) in registers
    const float* Qb = Q + (size_t)b*TT*DD + (size_t)h*HD;
    uint32_t qf[16][4];
    #pragma unroll
    for (int ks = 0; ks < 16; ks++) {
        const float* p0 = &Qb[(size_t)qr*DD + ks*8 + t4];
        qf[ks][0] = __float_as_uint(f2tf(p0[0]        * scale));
        qf[ks][1] = __float_as_uint(f2tf(p0[8*DD]     * scale));
        qf[ks][2] = __float_as_uint(f2tf(p0[4]        * scale));
        qf[ks][3] = __float_as_uint(f2tf(p0[8*DD + 4] * scale));
    }

    float of[16][4];
    #pragma unroll
    for (int nt = 0; nt < 16; nt++)
        #pragma unroll
        for (int e = 0; e < 4; e++) of[nt][e] = 0.f;

    float m_lo = -1e30f, m_hi = -1e30f, l_lo = 0.f, l_hi = 0.f;

    const float4* Kt = Kfp + (size_t)b*(TT/64)*2048;  // per-batch tiles
    const float4* Vt = Vfp + (size_t)b*(TT/64)*2048;
    const int nkt = 2*(qb + 1);

    auto fill = [&](int t) {
        const uint32_t dst = sb + (uint32_t)(t & 1) * 65536;
        const float4* sk = Kt + (size_t)t * 2048;
        const float4* sv = Vt + (size_t)t * 2048;
        #pragma unroll
        for (int i = 0; i < 8; i++) {
            const int idx = tid + i*256;
            asm volatile("cp.async.cg.shared.global [%0], [%1], 16;"
                         :: "r"(dst + idx*16), "l"(sk + idx));
            asm volatile("cp.async.cg.shared.global [%0], [%1], 16;"
                         :: "r"(dst + 32768 + idx*16), "l"(sv + idx));
        }
        asm volatile("cp.async.commit_group;" ::: "memory");
    };

    fill(0);
    for (int kt = 0; kt < nkt; kt++) {
        if (kt + 1 < nkt) { fill(kt + 1); asm volatile("cp.async.wait_group 1;" ::: "memory"); }
        else              { asm volatile("cp.async.wait_group 0;" ::: "memory"); }
        __syncthreads();

        const float4* Kf = (const float4*)sm + (size_t)(kt & 1) * F_STAGE_F4;
        const float4* Vf = Kf + 2048;
        const int k0 = kt * 64;

        // ---- S = Q @ K^T (paired B fragments: 1 LDS.128 -> 2 mma) ----
        float sacc[8][4];
        #pragma unroll
        for (int nt = 0; nt < 8; nt++)
            #pragma unroll
            for (int e = 0; e < 4; e++) sacc[nt][e] = 0.f;

        #pragma unroll
        for (int ks = 0; ks < 16; ks++) {
            #pragma unroll
            for (int g = 0; g < 4; g++) {
                float4 b4 = Kf[ks*128 + g*32 + lane];
                mma_tf32(sacc[2*g  ], qf[ks], (const uint32_t*)&b4.x);
                mma_tf32(sacc[2*g+1], qf[ks], (const uint32_t*)&b4.z);
            }
        }

        // ---- causal mask (only last two tiles overlap the diagonal) ----
        if (kt >= nkt - 2) {
            #pragma unroll
            for (int nt = 0; nt < 8; nt++) {
                int kc = k0 + nt*8 + 2*t4;
                if (kc     > qr)     sacc[nt][0] = -1e30f;
                if (kc + 1 > qr)     sacc[nt][1] = -1e30f;
                if (kc     > qr + 8) sacc[nt][2] = -1e30f;
                if (kc + 1 > qr + 8) sacc[nt][3] = -1e30f;
            }
        }

        // ---- online softmax ----
        float mx_lo = -1e30f, mx_hi = -1e30f;
        #pragma unroll
        for (int nt = 0; nt < 8; nt++) {
            mx_lo = fmaxf(mx_lo, fmaxf(sacc[nt][0], sacc[nt][1]));
            mx_hi = fmaxf(mx_hi, fmaxf(sacc[nt][2], sacc[nt][3]));
        }
        mx_lo = fmaxf(mx_lo, __shfl_xor_sync(0xffffffffu, mx_lo, 1));
        mx_lo = fmaxf(mx_lo, __shfl_xor_sync(0xffffffffu, mx_lo, 2));
        mx_hi = fmaxf(mx_hi, __shfl_xor_sync(0xffffffffu, mx_hi, 1));
        mx_hi = fmaxf(mx_hi, __shfl_xor_sync(0xffffffffu, mx_hi, 2));

        const float mn_lo = fmaxf(m_lo, mx_lo);
        const float mn_hi = fmaxf(m_hi, mx_hi);
        const float corr_lo = __expf(m_lo - mn_lo);
        const float corr_hi = __expf(m_hi - mn_hi);

        float sum_lo = 0.f, sum_hi = 0.f;
        #pragma unroll
        for (int nt = 0; nt < 8; nt++) {
            sacc[nt][0] = __expf(sacc[nt][0] - mn_lo);
            sacc[nt][1] = __expf(sacc[nt][1] - mn_lo);
            sacc[nt][2] = __expf(sacc[nt][2] - mn_hi);
            sacc[nt][3] = __expf(sacc[nt][3] - mn_hi);
            sum_lo += sacc[nt][0] + sacc[nt][1];
            sum_hi += sacc[nt][2] + sacc[nt][3];
        }
        sum_lo += __shfl_xor_sync(0xffffffffu, sum_lo, 1);
        sum_lo += __shfl_xor_sync(0xffffffffu, sum_lo, 2);
        sum_hi += __shfl_xor_sync(0xffffffffu, sum_hi, 1);
        sum_hi += __shfl_xor_sync(0xffffffffu, sum_hi, 2);

        l_lo = l_lo * corr_lo + sum_lo;  m_lo = mn_lo;
        l_hi = l_hi * corr_hi + sum_hi;  m_hi = mn_hi;

        #pragma unroll
        for (int nt = 0; nt < 16; nt++) {
            of[nt][0] *= corr_lo;  of[nt][1] *= corr_lo;
            of[nt][2] *= corr_hi;  of[nt][3] *= corr_hi;
        }

        // ---- P through per-warp smem (C-layout -> A-layout), tf32 ----
        #pragma unroll
        for (int nt = 0; nt < 8; nt++) {
            float2 p01 = make_float2(f2tf(sacc[nt][0]), f2tf(sacc[nt][1]));
            *(float2*)&Pw[grp*PS_ST + nt*8 + 2*t4] = p01;
            float2 p23 = make_float2(f2tf(sacc[nt][2]), f2tf(sacc[nt][3]));
            *(float2*)&Pw[(grp + 8)*PS_ST + nt*8 + 2*t4] = p23;
        }
        __syncwarp();

        // ---- O += P @ V (paired B fragments) ----
        #pragma unroll
        for (int ks = 0; ks < 8; ks++) {
            uint32_t pf[4];
            const float* pb = &Pw[grp*PS_ST + ks*8 + t4];
            pf[0] = __float_as_uint(pb[0]);
            pf[1] = __float_as_uint(pb[8*PS_ST]);
            pf[2] = __float_as_uint(pb[4]);
            pf[3] = __float_as_uint(pb[8*PS_ST + 4]);
            #pragma unroll
            for (int g = 0; g < 8; g++) {
                float4 b4 = Vf[ks*256 + g*32 + lane];
                mma_tf32(of[2*g  ], pf, (const uint32_t*)&b4.x);
                mma_tf32(of[2*g+1], pf, (const uint32_t*)&b4.z);
            }
        }
        __syncthreads();   // stage reads done before next fill overwrites
    }

    // ---- normalize, round to tf32, write DIRECTLY in packed A-fragment order ----
    // Element (m,k): m = b*TT + qr (+8 via reg), k = h*HD + nt*8 + 2*t4 + e.
    // float offset = (tile*1024 + ks*256 + mt*32 + grp*4 + (k&3))*4 + ((k>>2)&1)*2 + reghi
    const float inv_lo = 1.f / l_lo;
    const float inv_hi = 1.f / l_hi;
    {
        const int mglob = b*TT + qr;               // reghi=0 row
        const int mb = mglob >> 7;
        const int mt = (mglob >> 4) & 7;           // same for +8 row
        const size_t rowbase = ((size_t)mb*64)*1024 + (size_t)mt*32 + grp*4; // float4 units (tile kc added below)
        #pragma unroll
        for (int nt = 0; nt < 16; nt++) {
            #pragma unroll
            for (int e = 0; e < 2; e++) {
                const int k = h*HD + nt*8 + 2*t4 + e;
                const int kc = k >> 5;
                const int ks = (k >> 3) & 3;
                const size_t slot4 = rowbase + (size_t)kc*1024 + ks*256 + (k & 3);
                const size_t off = slot4*4 + (size_t)((k >> 2) & 1)*2;
                AOp[off    ] = f2tf(of[nt][e]     * inv_lo);   // reghi=0
                AOp[off + 1] = f2tf(of[nt][e + 2] * inv_hi);   // reghi=1
            }
        }
    }
}

// ---------------- launch ----------------
extern "C" void kernel_launch(void* const* d_in, const int* in_sizes, int n_in,
                              void* d_out, int out_size)
{
    const float* x  = (const float*)d_in[0];
    const float* Wq = (const float*)d_in[1];
    const float* bq = (const float*)d_in[2];
    const float* Wk = (const float*)d_in[3];
    const float* bk = (const float*)d_in[4];
    const float* Wv = (const float*)d_in[5];
    const float* bv = (const float*)d_in[6];
    const float* Wo = (const float*)d_in[7];
    const float* bo = (const float*)d_in[8];
    float* out = (float*)d_out;

    float *Qp, *Kp, *Vp;
    float4 *Kfp, *Vfp;
    float4 *Xp, *AOp, *WqP, *WkvP, *WoP;
    cudaGetSymbolAddress((void**)&Qp,   g_Q);
    cudaGetSymbolAddress((void**)&Kp,   g_K);
    cudaGetSymbolAddress((void**)&Vp,   g_V);
    cudaGetSymbolAddress((void**)&Kfp,  g_Kf);
    cudaGetSymbolAddress((void**)&Vfp,  g_Vf);
    cudaGetSymbolAddress((void**)&Xp,   g_Xp);
    cudaGetSymbolAddress((void**)&AOp,  g_AOp);
    cudaGetSymbolAddress((void**)&WqP,  g_WqP);
    cudaGetSymbolAddress((void**)&WkvP, g_WkvP);
    cudaGetSymbolAddress((void**)&WoP,  g_WoP);

    cudaFuncSetAttribute(gemm_mma,  cudaFuncAttributeMaxDynamicSharedMemorySize, G_SMEM);
    cudaFuncSetAttribute(gemm_kv,   cudaFuncAttributeMaxDynamicSharedMemorySize, G_SMEM);
    cudaFuncSetAttribute(flash_tf32, cudaFuncAttributeMaxDynamicSharedMemorySize, FLASH_SMEM);

    // ---- pack GEMM operands (tf32-rounded, fragment order) ----
    pack_A <<<MROWS*DD/4/256, 256>>>(x,  Xp,  MROWS, DD);
    pack_B2<<<DD*DD/4/256,    256>>>(Wq, WqP, DD, DD);
    pack_B2<<<DD*HD/4/256,    256>>>(Wk, WkvP, HD, DD);
    pack_B2<<<DD*HD/4/256,    256>>>(Wv, WkvP + DD*HD/4, HD, DD);
    pack_B2<<<DD*DD/4/256,    256>>>(Wo, WoP, DD, DD);

    // ---- projections ----
    gemm_mma<<<dim3(DD/128, MROWS/128), 256, G_SMEM>>>(Xp, WqP, bq, Qp, MROWS, DD, DD);
    gemm_kv <<<dim3(2,      MROWS/128), 256, G_SMEM>>>(Xp, WkvP, bk, bv, Kp, Vp, DD);

    // ---- pack K/V into paired-fragment tiles ----
    pack_kv<<<2*KV_TILES*2048/256, 256>>>(Kp, Vp, Kfp, Vfp);

    // ---- attention (writes AOp directly in packed A-fragment order) ----
    flash_tf32<<<dim3(TT/FB_R, HH, BB), 256, FLASH_SMEM>>>(Qp, Kfp, Vfp, (float*)AOp);

    // ---- output projection ----
    gemm_mma<<<dim3(DD/128, MROWS/128), 256, G_SMEM>>>(AOp, WoP, bo, out, MROWS, DD, DD);
}

// round 16
// speedup vs baseline: 1.1169x; 1.1028x over previous
#include <cuda_runtime.h>
#include <cuda_bf16.h>
#include <math.h>
#include <stdint.h>

// Problem constants (MultiQueryAttention_56358560858478)
#define BB 2
#define TT 2048
#define DD 2048
#define HH 16
#define HD 128
#define MROWS (BB*TT)   // 4096
#define KV_TILES (MROWS/64)   // 64 tiles of 64 keys (both batches)

// ---------------- scratch (no allocation allowed) ----------------
__device__ float  g_Q [MROWS * DD];       // Q projection (B,T,D)
__device__ float4 g_Kf[KV_TILES * 2048];  // K paired-fragment tiles (written by gemm_qkv)
__device__ float4 g_Vf[KV_TILES * 2048];  // V paired-fragment tiles
__device__ float4 g_Xp [MROWS * DD / 4];  // x packed (A-fragment order, tf32)
__device__ float4 g_AOp[MROWS * DD / 4];  // AO packed (written directly by flash)
__device__ float4 g_WqP[DD * DD / 4];     // weights packed (paired B-fragment order)
__device__ float4 g_WkvP[2 * DD * HD / 4];// Wk|Wv packed back-to-back
__device__ float4 g_WoP[DD * DD / 4];

// ---------------- helpers ----------------
__device__ __forceinline__ float f2tf(float x) {
    uint32_t u;
    asm("cvt.rna.tf32.f32 %0, %1;" : "=r"(u) : "f"(x));
    return __uint_as_float(u);
}

__device__ __forceinline__ uint32_t s2u(const void* p) {
    uint32_t a;
    asm("{ .reg .u64 t; cvta.to.shared.u64 t, %1; cvt.u32.u64 %0, t; }" : "=r"(a) : "l"(p));
    return a;
}

__device__ __forceinline__ void mma_tf32(float* d, const uint32_t* a, const uint32_t* b) {
    asm volatile(
        "mma.sync.aligned.m16n8k8.row.col.f32.tf32.tf32.f32 "
        "{%0,%1,%2,%3}, {%4,%5,%6,%7}, {%8,%9}, {%0,%1,%2,%3};"
        : "+f"(d[0]), "+f"(d[1]), "+f"(d[2]), "+f"(d[3])
        : "r"(a[0]), "r"(a[1]), "r"(a[2]), "r"(a[3]), "r"(b[0]), "r"(b[1]));
}

// ================= operand packing (device bodies) =================
__device__ __forceinline__
void pack_A_elem(const float* __restrict__ src, float4* __restrict__ dst,
                 int K, int o)
{
    const int lane = o & 31;
    const int mt   = (o >> 5) & 7;
    const int ks   = (o >> 8) & 3;
    const int tile = o >> 10;
    const int KT = K >> 5;
    const int kc = tile % KT;
    const int mb = tile / KT;
    const int m = mb*128 + mt*16 + (lane >> 2);
    const int k = kc*32 + ks*8 + (lane & 3);
    const float* s = src + (size_t)m * K + k;
    float4 v;
    v.x = f2tf(s[0]);
    v.y = f2tf(s[(size_t)8 * K]);
    v.z = f2tf(s[4]);
    v.w = f2tf(s[(size_t)8 * K + 4]);
    dst[o] = v;
}

// Paired B fragments: float4 = {W[k][n], W[k+4][n], W[k][n+8], W[k+4][n+8]}
__device__ __forceinline__
void pack_B2_elem(const float* __restrict__ src, float4* __restrict__ dst,
                  int N, int K, int o)
{
    const int lane = o & 31;
    const int ng2  = (o >> 5) & 7;
    const int ks   = (o >> 8) & 3;
    const int tile = o >> 10;
    const int KT = K >> 5;
    const int kc = tile % KT;
    const int nb = tile / KT;
    const int n = nb*128 + ng2*16 + (lane >> 2);
    const int k = kc*32 + ks*8 + (lane & 3);
    const float* s = src + (size_t)k * N + n;
    dst[o] = make_float4(f2tf(s[0]), f2tf(s[(size_t)4*N]),
                         f2tf(s[8]), f2tf(s[(size_t)4*N + 8]));
}

// One launch for all operand packing.
// Regions (blocks): [0,8192) x->Xp | [8192,12288) Wq | [12288,12544) Wk |
//                   [12544,12800) Wv | [12800,16896) Wo
#define PACK_BLOCKS 16896
__global__ void pack_all(const float* __restrict__ x,
                         const float* __restrict__ Wq, const float* __restrict__ Wk,
                         const float* __restrict__ Wv, const float* __restrict__ Wo,
                         float4* __restrict__ Xp, float4* __restrict__ WqP,
                         float4* __restrict__ WkvP, float4* __restrict__ WoP)
{
    const int blk = blockIdx.x;
    const int tid = threadIdx.x;
    if (blk < 8192) {
        pack_A_elem(x, Xp, DD, blk*256 + tid);
    } else if (blk < 12288) {
        pack_B2_elem(Wq, WqP, DD, DD, (blk - 8192)*256 + tid);
    } else if (blk < 12544) {
        pack_B2_elem(Wk, WkvP, HD, DD, (blk - 12288)*256 + tid);
    } else if (blk < 12800) {
        pack_B2_elem(Wv, WkvP + DD*HD/4, HD, DD, (blk - 12544)*256 + tid);
    } else {
        pack_B2_elem(Wo, WoP, DD, DD, (blk - 12800)*256 + tid);
    }
}

// ================= mma.sync GEMM body (B2 paired loads) =================
// MODE 0: row-major C (no rounding). MODE 1: K paired-fragment scatter (tf32).
// MODE 2: V paired-fragment scatter (tf32).
#define G_STAGE_F 8192
#define G_SMEM (3 * G_STAGE_F * 4)

template<int MODE>
__device__ __forceinline__
void gemm_body(const float4* At, const float4* Bt, const float* bias,
               float* C, int N, int KT, int mb, int ncol0, float* sm)
{
    const int tid = threadIdx.x, lane = tid & 31, wid = tid >> 5;
    const int grp = lane >> 2, t4 = lane & 3;
    const int NC = KT;

    float acc[2][8][4];
    #pragma unroll
    for (int i = 0; i < 2; i++)
        #pragma unroll
        for (int j = 0; j < 8; j++)
            #pragma unroll
            for (int e = 0; e < 4; e++) acc[i][j][e] = 0.f;

    auto fill = [&](int ch) {
        const int s = ch % 3;
        const uint32_t da = s2u(sm + s * G_STAGE_F);
        const float4* a = At + (size_t)ch * 1024;
        const float4* b = Bt + (size_t)ch * 1024;
        #pragma unroll
        for (int i = tid; i < 1024; i += 256)
            asm volatile("cp.async.cg.shared.global [%0], [%1], 16;"
                         :: "r"(da + i*16), "l"(a + i));
        const uint32_t db = da + 4096*4;
        #pragma unroll
        for (int i = tid; i < 1024; i += 256)
            asm volatile("cp.async.cg.shared.global [%0], [%1], 16;"
                         :: "r"(db + i*16), "l"(b + i));
        asm volatile("cp.async.commit_group;" ::: "memory");
    };

    fill(0);
    if (NC > 1) fill(1);

    const int mtb  = (wid & 3) * 2;     // warp's first 16-row tile
    const int ngb2 = (wid >> 2) * 4;    // warp's first paired-n group (16 cols each)

    for (int i = 0; i < NC; i++) {
        if (i + 2 < NC) asm volatile("cp.async.wait_group 1;" ::: "memory");
        else            asm volatile("cp.async.wait_group 0;" ::: "memory");
        __syncthreads();
        if (i + 2 < NC) fill(i + 2);

        const float* sa = sm + (i % 3) * G_STAGE_F;
        const float* sb = sa + 4096;
        #pragma unroll
        for (int ks = 0; ks < 4; ks++) {
            float4 a0 = *(const float4*)&sa[ks*1024 + (mtb + 0)*128 + lane*4];
            float4 a1 = *(const float4*)&sa[ks*1024 + (mtb + 1)*128 + lane*4];
            #pragma unroll
            for (int g = 0; g < 4; g++) {
                float4 b4 = *(const float4*)&sb[ks*1024 + (ngb2 + g)*128 + lane*4];
                mma_tf32(acc[0][2*g  ], (const uint32_t*)&a0, (const uint32_t*)&b4.x);
                mma_tf32(acc[0][2*g+1], (const uint32_t*)&a0, (const uint32_t*)&b4.z);
                mma_tf32(acc[1][2*g  ], (const uint32_t*)&a1, (const uint32_t*)&b4.x);
                mma_tf32(acc[1][2*g+1], (const uint32_t*)&a1, (const uint32_t*)&b4.z);
            }
        }
        __syncthreads();
    }

    if (MODE == 0) {
        #pragma unroll
        for (int mt2 = 0; mt2 < 2; mt2++) {
            const int r = mb*128 + (wid & 3)*32 + mt2*16 + grp;
            #pragma unroll
            for (int nt = 0; nt < 8; nt++) {
                const int c = ncol0 + (wid >> 2)*64 + nt*8 + 2*t4;
                const float bz0 = bias[c], bz1 = bias[c+1];
                *(float2*)&C[(size_t)r*N + c] =
                    make_float2(acc[mt2][nt][0] + bz0, acc[mt2][nt][1] + bz1);
                *(float2*)&C[(size_t)(r+8)*N + c] =
                    make_float2(acc[mt2][nt][2] + bz0, acc[mt2][nt][3] + bz1);
            }
        }
    } else {
        // Scatter into paired-fragment tile layout (values tf32-rounded).
        #pragma unroll
        for (int mt2 = 0; mt2 < 2; mt2++) {
            #pragma unroll
            for (int nt = 0; nt < 8; nt++) {
                const int cbase = (wid >> 2)*64 + nt*8 + 2*t4;
                #pragma unroll
                for (int e = 0; e < 4; e++) {
                    const int r = mb*128 + (wid & 3)*32 + mt2*16 + grp + ((e >= 2) ? 8 : 0);
                    const int c = cbase + (e & 1);
                    const float val = f2tf(acc[mt2][nt][e] + bias[c]);
                    const int tile = r >> 6;
                    const int rr = r & 63;
                    size_t idx;
                    if (MODE == 1) {
                        // Kf[tile][ks16][g4][lane]: r=tile*64+g*16+(lane>>2), col=ks*8+(lane&3)
                        const int g = rr >> 4;
                        const int w16 = rr & 15;
                        const int comp = ((w16 >= 8) ? 2 : 0) + (((c & 7) >= 4) ? 1 : 0);
                        const int lane_f = (w16 & 7)*4 + (c & 3);
                        idx = (size_t)tile*8192 + ((size_t)(c >> 3)*128 + g*32 + lane_f)*4 + comp;
                    } else {
                        // Vf[tile][ks8][g8][lane]: key=tile*64+ks*8+(lane&3), n=g*16+(lane>>2)
                        const int ks = rr >> 3;
                        const int w8 = rr & 7;
                        const int comp = ((w8 >= 4) ? 1 : 0) + (((c & 15) >= 8) ? 2 : 0);
                        const int lane_f = (c & 7)*4 + (rr & 3);
                        idx = (size_t)tile*8192 + ((size_t)ks*256 + (c >> 4)*32 + lane_f)*4 + comp;
                    }
                    C[idx] = val;
                }
            }
        }
    }
}

// Fused Q/K/V projection: blockIdx.x 0..15 = Q tiles, 16 = K (packed), 17 = V (packed)
__global__ __launch_bounds__(256)
void gemm_qkv(const float4* __restrict__ Xp, const float4* __restrict__ WqP,
              const float4* __restrict__ WkvP,
              const float* __restrict__ bq, const float* __restrict__ bk,
              const float* __restrict__ bv,
              float* __restrict__ Qout, float* __restrict__ Kf, float* __restrict__ Vf)
{
    extern __shared__ float sm[];
    const int KT = DD >> 5;
    const float4* At = Xp + (size_t)blockIdx.y * KT * 1024;
    if (blockIdx.x < 16) {
        gemm_body<0>(At, WqP + (size_t)blockIdx.x * KT * 1024,
                     bq, Qout, DD, KT, blockIdx.y, blockIdx.x * 128, sm);
    } else if (blockIdx.x == 16) {
        gemm_body<1>(At, WkvP, bk, Kf, HD, KT, blockIdx.y, 0, sm);
    } else {
        gemm_body<2>(At, WkvP + DD*HD/4, bv, Vf, HD, KT, blockIdx.y, 0, sm);
    }
}

__global__ __launch_bounds__(256)
void gemm_mma(const float4* __restrict__ Ap, const float4* __restrict__ Bp,
              const float* __restrict__ bias, float* __restrict__ C,
              int M, int N, int K)
{
    extern __shared__ float sm[];
    const int KT = K >> 5;
    gemm_body<0>(Ap + (size_t)blockIdx.y * KT * 1024,
                 Bp + (size_t)blockIdx.x * KT * 1024,
                 bias, C, N, KT, blockIdx.y, blockIdx.x * 128, sm);
}

// ---------------- flash attention: paired K/V tiles, packed-AO epilogue ----
#define FB_R 128
#define PS_ST 68
#define F_STAGE_F4 4096                             // float4 per stage
#define PW_OFF (2*F_STAGE_F4*4)                     // float offset of Pw region
#define FLASH_SMEM ((PW_OFF + 8*16*PS_ST) * 4)      // 165888 B

__global__ __launch_bounds__(256)
void flash_tf32(const float* __restrict__ Q,
                const float4* __restrict__ Kfp, const float4* __restrict__ Vfp,
                float* __restrict__ AOp)        // packed A-fragment output
{
    extern __shared__ float sm[];
    const uint32_t sb = s2u(sm);

    const int tid  = threadIdx.x;
    const int lane = tid & 31;
    const int wid  = tid >> 5;
    const int grp  = lane >> 2;
    const int t4   = lane & 3;
    float* Pw = sm + PW_OFF + wid*16*PS_ST;

    const int qb = gridDim.x - 1 - blockIdx.x;   // longest blocks first
    const int h  = blockIdx.y;
    const int b  = blockIdx.z;
    const int q0 = qb * FB_R;
    const int qr = q0 + wid*16 + grp;

    const float scale = 0.08838834764831845f;

    const float* Qb = Q + (size_t)b*TT*DD + (size_t)h*HD;
    uint32_t qf[16][4];
    #pragma unroll
    for (int ks = 0; ks < 16; ks++) {
        const float* p0 = &Qb[(size_t)qr*DD + ks*8 + t4];
        qf[ks][0] = __float_as_uint(f2tf(p0[0]        * scale));
        qf[ks][1] = __float_as_uint(f2tf(p0[8*DD]     * scale));
        qf[ks][2] = __float_as_uint(f2tf(p0[4]        * scale));
        qf[ks][3] = __float_as_uint(f2tf(p0[8*DD + 4] * scale));
    }

    float of[16][4];
    #pragma unroll
    for (int nt = 0; nt < 16; nt++)
        #pragma unroll
        for (int e = 0; e < 4; e++) of[nt][e] = 0.f;

    float m_lo = -1e30f, m_hi = -1e30f, l_lo = 0.f, l_hi = 0.f;

    const float4* Kt = Kfp + (size_t)b*(TT/64)*2048;  // per-batch tiles
    const float4* Vt = Vfp + (size_t)b*(TT/64)*2048;
    const int nkt = 2*(qb + 1);

    auto fill = [&](int t) {
        const uint32_t dst = sb + (uint32_t)(t & 1) * 65536;
        const float4* sk = Kt + (size_t)t * 2048;
        const float4* sv = Vt + (size_t)t * 2048;
        #pragma unroll
        for (int i = 0; i < 8; i++) {
            const int idx = tid + i*256;
            asm volatile("cp.async.cg.shared.global [%0], [%1], 16;"
                         :: "r"(dst + idx*16), "l"(sk + idx));
            asm volatile("cp.async.cg.shared.global [%0], [%1], 16;"
                         :: "r"(dst + 32768 + idx*16), "l"(sv + idx));
        }
        asm volatile("cp.async.commit_group;" ::: "memory");
    };

    fill(0);
    for (int kt = 0; kt < nkt; kt++) {
        if (kt + 1 < nkt) { fill(kt + 1); asm volatile("cp.async.wait_group 1;" ::: "memory"); }
        else              { asm volatile("cp.async.wait_group 0;" ::: "memory"); }
        __syncthreads();

        const float4* Kf = (const float4*)sm + (size_t)(kt & 1) * F_STAGE_F4;
        const float4* Vf = Kf + 2048;
        const int k0 = kt * 64;

        // ---- S = Q @ K^T (paired B fragments) ----
        float sacc[8][4];
        #pragma unroll
        for (int nt = 0; nt < 8; nt++)
            #pragma unroll
            for (int e = 0; e < 4; e++) sacc[nt][e] = 0.f;

        #pragma unroll
        for (int ks = 0; ks < 16; ks++) {
            #pragma unroll
            for (int g = 0; g < 4; g++) {
                float4 b4 = Kf[ks*128 + g*32 + lane];
                mma_tf32(sacc[2*g  ], qf[ks], (const uint32_t*)&b4.x);
                mma_tf32(sacc[2*g+1], qf[ks], (const uint32_t*)&b4.z);
            }
        }

        // ---- causal mask ----
        if (kt >= nkt - 2) {
            #pragma unroll
            for (int nt = 0; nt < 8; nt++) {
                int kc = k0 + nt*8 + 2*t4;
                if (kc     > qr)     sacc[nt][0] = -1e30f;
                if (kc + 1 > qr)     sacc[nt][1] = -1e30f;
                if (kc     > qr + 8) sacc[nt][2] = -1e30f;
                if (kc + 1 > qr + 8) sacc[nt][3] = -1e30f;
            }
        }

        // ---- online softmax ----
        float mx_lo = -1e30f, mx_hi = -1e30f;
        #pragma unroll
        for (int nt = 0; nt < 8; nt++) {
            mx_lo = fmaxf(mx_lo, fmaxf(sacc[nt][0], sacc[nt][1]));
            mx_hi = fmaxf(mx_hi, fmaxf(sacc[nt][2], sacc[nt][3]));
        }
        mx_lo = fmaxf(mx_lo, __shfl_xor_sync(0xffffffffu, mx_lo, 1));
        mx_lo = fmaxf(mx_lo, __shfl_xor_sync(0xffffffffu, mx_lo, 2));
        mx_hi = fmaxf(mx_hi, __shfl_xor_sync(0xffffffffu, mx_hi, 1));
        mx_hi = fmaxf(mx_hi, __shfl_xor_sync(0xffffffffu, mx_hi, 2));

        const float mn_lo = fmaxf(m_lo, mx_lo);
        const float mn_hi = fmaxf(m_hi, mx_hi);
        const float corr_lo = __expf(m_lo - mn_lo);
        const float corr_hi = __expf(m_hi - mn_hi);

        float sum_lo = 0.f, sum_hi = 0.f;
        #pragma unroll
        for (int nt = 0; nt < 8; nt++) {
            sacc[nt][0] = __expf(sacc[nt][0] - mn_lo);
            sacc[nt][1] = __expf(sacc[nt][1] - mn_lo);
            sacc[nt][2] = __expf(sacc[nt][2] - mn_hi);
            sacc[nt][3] = __expf(sacc[nt][3] - mn_hi);
            sum_lo += sacc[nt][0] + sacc[nt][1];
            sum_hi += sacc[nt][2] + sacc[nt][3];
        }
        sum_lo += __shfl_xor_sync(0xffffffffu, sum_lo, 1);
        sum_lo += __shfl_xor_sync(0xffffffffu, sum_lo, 2);
        sum_hi += __shfl_xor_sync(0xffffffffu, sum_hi, 1);
        sum_hi += __shfl_xor_sync(0xffffffffu, sum_hi, 2);

        l_lo = l_lo * corr_lo + sum_lo;  m_lo = mn_lo;
        l_hi = l_hi * corr_hi + sum_hi;  m_hi = mn_hi;

        #pragma unroll
        for (int nt = 0; nt < 16; nt++) {
            of[nt][0] *= corr_lo;  of[nt][1] *= corr_lo;
            of[nt][2] *= corr_hi;  of[nt][3] *= corr_hi;
        }

        // ---- P through per-warp smem (C-layout -> A-layout), tf32 ----
        #pragma unroll
        for (int nt = 0; nt < 8; nt++) {
            float2 p01 = make_float2(f2tf(sacc[nt][0]), f2tf(sacc[nt][1]));
            *(float2*)&Pw[grp*PS_ST + nt*8 + 2*t4] = p01;
            float2 p23 = make_float2(f2tf(sacc[nt][2]), f2tf(sacc[nt][3]));
            *(float2*)&Pw[(grp + 8)*PS_ST + nt*8 + 2*t4] = p23;
        }
        __syncwarp();

        // ---- O += P @ V (paired B fragments) ----
        #pragma unroll
        for (int ks = 0; ks < 8; ks++) {
            uint32_t pf[4];
            const float* pb = &Pw[grp*PS_ST + ks*8 + t4];
            pf[0] = __float_as_uint(pb[0]);
            pf[1] = __float_as_uint(pb[8*PS_ST]);
            pf[2] = __float_as_uint(pb[4]);
            pf[3] = __float_as_uint(pb[8*PS_ST + 4]);
            #pragma unroll
            for (int g = 0; g < 8; g++) {
                float4 b4 = Vf[ks*256 + g*32 + lane];
                mma_tf32(of[2*g  ], pf, (const uint32_t*)&b4.x);
                mma_tf32(of[2*g+1], pf, (const uint32_t*)&b4.z);
            }
        }
        __syncthreads();   // stage reads done before next fill overwrites
    }

    // ---- normalize, round to tf32, write DIRECTLY in packed A-fragment order ----
    const float inv_lo = 1.f / l_lo;
    const float inv_hi = 1.f / l_hi;
    {
        const int mglob = b*TT + qr;               // reghi=0 row
        const int mb = mglob >> 7;
        const int mt = (mglob >> 4) & 7;
        const size_t rowbase = ((size_t)mb*64)*1024 + (size_t)mt*32 + grp*4;
        #pragma unroll
        for (int nt = 0; nt < 16; nt++) {
            #pragma unroll
            for (int e = 0; e < 2; e++) {
                const int k = h*HD + nt*8 + 2*t4 + e;
                const int kc = k >> 5;
                const int ks = (k >> 3) & 3;
                const size_t slot4 = rowbase + (size_t)kc*1024 + ks*256 + (k & 3);
                const size_t off = slot4*4 + (size_t)((k >> 2) & 1)*2;
                AOp[off    ] = f2tf(of[nt][e]     * inv_lo);   // reghi=0
                AOp[off + 1] = f2tf(of[nt][e + 2] * inv_hi);   // reghi=1
            }
        }
    }
}

// ---------------- launch ----------------
extern "C" void kernel_launch(void* const* d_in, const int* in_sizes, int n_in,
                              void* d_out, int out_size)
{
    const float* x  = (const float*)d_in[0];
    const float* Wq = (const float*)d_in[1];
    const float* bq = (const float*)d_in[2];
    const float* Wk = (const float*)d_in[3];
    const float* bk = (const float*)d_in[4];
    const float* Wv = (const float*)d_in[5];
    const float* bv = (const float*)d_in[6];
    const float* Wo = (const float*)d_in[7];
    const float* bo = (const float*)d_in[8];
    float* out = (float*)d_out;

    float *Qp;
    float4 *Kfp, *Vfp, *Xp, *AOp, *WqP, *WkvP, *WoP;
    cudaGetSymbolAddress((void**)&Qp,   g_Q);
    cudaGetSymbolAddress((void**)&Kfp,  g_Kf);
    cudaGetSymbolAddress((void**)&Vfp,  g_Vf);
    cudaGetSymbolAddress((void**)&Xp,   g_Xp);
    cudaGetSymbolAddress((void**)&AOp,  g_AOp);
    cudaGetSymbolAddress((void**)&WqP,  g_WqP);
    cudaGetSymbolAddress((void**)&WkvP, g_WkvP);
    cudaGetSymbolAddress((void**)&WoP,  g_WoP);

    cudaFuncSetAttribute(gemm_qkv,  cudaFuncAttributeMaxDynamicSharedMemorySize, G_SMEM);
    cudaFuncSetAttribute(gemm_mma,  cudaFuncAttributeMaxDynamicSharedMemorySize, G_SMEM);
    cudaFuncSetAttribute(flash_tf32, cudaFuncAttributeMaxDynamicSharedMemorySize, FLASH_SMEM);

    // ---- pack all operands in one launch ----
    pack_all<<<PACK_BLOCKS, 256>>>(x, Wq, Wk, Wv, Wo, Xp, WqP, WkvP, WoP);

    // ---- fused Q/K/V projections (K/V write paired-fragment tiles directly) ----
    gemm_qkv<<<dim3(18, MROWS/128), 256, G_SMEM>>>(Xp, WqP, WkvP, bq, bk, bv,
                                                   Qp, (float*)Kfp, (float*)Vfp);

    // ---- attention (writes AOp directly in packed A-fragment order) ----
    flash_tf32<<<dim3(TT/FB_R, HH, BB), 256, FLASH_SMEM>>>(Qp, Kfp, Vfp, (float*)AOp);

    // ---- output projection ----
    gemm_mma<<<dim3(DD/128, MROWS/128), 256, G_SMEM>>>(AOp, WoP, bo, out, MROWS, DD, DD);
}

// round 17
// speedup vs baseline: 1.9032x; 1.7040x over previous
#include <cuda_runtime.h>
#include <cuda_fp16.h>
#include <math.h>
#include <stdint.h>

// Problem constants (MultiQueryAttention_56358560858478)
#define BB 2
#define TT 2048
#define DD 2048
#define HH 16
#define HD 128
#define MROWS (BB*TT)   // 4096
#define KV_TILES (MROWS/64)   // 64 tiles of 64 keys (both batches)

// ---------------- scratch (no allocation allowed) ----------------
__device__ float g_Q  [MROWS * DD];          // Q projection fp32 (B,T,D)
__device__ uint4 g_Kfh[KV_TILES * 1024];     // K fp16 paired-fragment tiles
__device__ uint4 g_Vfh[KV_TILES * 1024];     // V fp16 paired-fragment tiles
__device__ uint4 g_Xph [1024 * 1024];        // x packed fp16 A-frag (32x32 tiles)
__device__ uint4 g_AOph[1024 * 1024];        // AO packed fp16 A-frag
__device__ uint4 g_WqPh[512 * 1024];         // Wq packed fp16 paired B-frag
__device__ uint4 g_WkvPh[2 * 32 * 1024];     // Wk|Wv packed
__device__ uint4 g_WoPh[512 * 1024];         // Wo packed

// ---------------- helpers ----------------
__device__ __forceinline__ uint32_t pk(float a, float b) {
    __half2 h = __halves2half2(__float2half_rn(a), __float2half_rn(b));
    return *(uint32_t*)&h;
}

__device__ __forceinline__ uint32_t s2u(const void* p) {
    uint32_t a;
    asm("{ .reg .u64 t; cvta.to.shared.u64 t, %1; cvt.u32.u64 %0, t; }" : "=r"(a) : "l"(p));
    return a;
}

__device__ __forceinline__ void mma_f16(float* d, const uint32_t* a, uint32_t b0, uint32_t b1) {
    asm volatile(
        "mma.sync.aligned.m16n8k16.row.col.f32.f16.f16.f32 "
        "{%0,%1,%2,%3}, {%4,%5,%6,%7}, {%8,%9}, {%0,%1,%2,%3};"
        : "+f"(d[0]), "+f"(d[1]), "+f"(d[2]), "+f"(d[3])
        : "r"(a[0]), "r"(a[1]), "r"(a[2]), "r"(a[3]), "r"(b0), "r"(b1));
}

// ================= operand packing (fp16, K-chunk 64) =================
// A-frag tile [mb][kc64]: uint4 idx = ks(4)*256 + mt(8)*32 + lane.
// 8 halves = {(m,k),(m,k+1),(m+8,k),(m+8,k+1),(m,k+8),(m,k+9),(m+8,k+8),(m+8,k+9)}
// m = mb*128+mt*16+(lane>>2), k = kc*64+ks*16+(lane&3)*2
__device__ __forceinline__
void pack_Ah_elem(const float* __restrict__ src, uint4* __restrict__ dst, int K, int o)
{
    const int lane = o & 31;
    const int mt = (o >> 5) & 7;
    const int ks = (o >> 8) & 3;
    const int tile = o >> 10;
    const int KT = K >> 6;
    const int kc = tile % KT;
    const int mb = tile / KT;
    const int m = mb*128 + mt*16 + (lane >> 2);
    const int k = kc*64 + ks*16 + (lane & 3)*2;
    const float* s = src + (size_t)m * K + k;
    const float* s8 = s + (size_t)8 * K;
    uint4 v;
    v.x = pk(s[0],  s[1]);
    v.y = pk(s8[0], s8[1]);
    v.z = pk(s[8],  s[9]);
    v.w = pk(s8[8], s8[9]);
    dst[o] = v;
}

// Paired B-frag tile [nb][kc64]: uint4 idx = ks(4)*256 + ng2(8)*32 + lane.
// 8 halves = {(k,n),(k+1,n),(k+8,n),(k+9,n),(k,n+8),(k+1,n+8),(k+8,n+8),(k+9,n+8)}
// n = nb*128+ng2*16+(lane>>2), k = kc*64+ks*16+(lane&3)*2;  W row-major [K][N]
__device__ __forceinline__
void pack_Bh_elem(const float* __restrict__ src, uint4* __restrict__ dst, int N, int K, int o)
{
    const int lane = o & 31;
    const int ng2 = (o >> 5) & 7;
    const int ks = (o >> 8) & 3;
    const int tile = o >> 10;
    const int KT = K >> 6;
    const int kc = tile % KT;
    const int nb = tile / KT;
    const int n = nb*128 + ng2*16 + (lane >> 2);
    const int k = kc*64 + ks*16 + (lane & 3)*2;
    const float* s = src + (size_t)k * N + n;
    uint4 v;
    v.x = pk(s[0],             s[(size_t)N]);
    v.y = pk(s[(size_t)8*N],   s[(size_t)9*N]);
    v.z = pk(s[8],             s[(size_t)N + 8]);
    v.w = pk(s[(size_t)8*N+8], s[(size_t)9*N + 8]);
    dst[o] = v;
}

// Regions (blocks of 256): x[0,4096) Wq[4096,6144) Wk[6144,6272) Wv[6272,6400) Wo[6400,8448)
#define PACK_BLOCKS 8448
__global__ void pack_all(const float* __restrict__ x,
                         const float* __restrict__ Wq, const float* __restrict__ Wk,
                         const float* __restrict__ Wv, const float* __restrict__ Wo)
{
    const int blk = blockIdx.x;
    const int tid = threadIdx.x;
    if (blk < 4096)      pack_Ah_elem(x,  g_Xph,  DD, blk*256 + tid);
    else if (blk < 6144) pack_Bh_elem(Wq, g_WqPh, DD, DD, (blk - 4096)*256 + tid);
    else if (blk < 6272) pack_Bh_elem(Wk, g_WkvPh, HD, DD, (blk - 6144)*256 + tid);
    else if (blk < 6400) pack_Bh_elem(Wv, g_WkvPh + 32768, HD, DD, (blk - 6272)*256 + tid);
    else                 pack_Bh_elem(Wo, g_WoPh, DD, DD, (blk - 6400)*256 + tid);
}

// ================= fp16 mma GEMM body, K-chunk 64 =================
// MODE 0: fp32 row-major C. MODE 1: K fp16 fragment scatter. MODE 2: V scatter.
#define G_STAGE_U4 2048                      // uint4 per stage (A 1024 + B 1024)
#define G_SMEM (3 * G_STAGE_U4 * 16)         // 96 KB

template<int MODE>
__device__ __forceinline__
void gemm_body(const uint4* At, const uint4* Bt, const float* bias,
               void* Cv, int N, int KT, int mb, int ncol0, char* smraw)
{
    const int tid = threadIdx.x, lane = tid & 31, wid = tid >> 5;
    const int grp = lane >> 2, t4 = lane & 3;
    const int NC = KT;
    uint4* smu = (uint4*)smraw;

    float acc[2][8][4];
    #pragma unroll
    for (int i = 0; i < 2; i++)
        #pragma unroll
        for (int j = 0; j < 8; j++)
            #pragma unroll
            for (int e = 0; e < 4; e++) acc[i][j][e] = 0.f;

    auto fill = [&](int ch) {
        const int s = ch % 3;
        const uint32_t da = s2u(smraw) + (uint32_t)s * G_STAGE_U4 * 16;
        const uint4* a = At + (size_t)ch * 1024;
        const uint4* b = Bt + (size_t)ch * 1024;
        #pragma unroll
        for (int i = tid; i < 1024; i += 256)
            asm volatile("cp.async.cg.shared.global [%0], [%1], 16;"
                         :: "r"(da + i*16), "l"(a + i));
        const uint32_t db = da + 1024*16;
        #pragma unroll
        for (int i = tid; i < 1024; i += 256)
            asm volatile("cp.async.cg.shared.global [%0], [%1], 16;"
                         :: "r"(db + i*16), "l"(b + i));
        asm volatile("cp.async.commit_group;" ::: "memory");
    };

    fill(0);
    if (NC > 1) fill(1);

    const int mtb  = (wid & 3) * 2;
    const int ngb2 = (wid >> 2) * 4;

    for (int i = 0; i < NC; i++) {
        if (i + 2 < NC) asm volatile("cp.async.wait_group 1;" ::: "memory");
        else            asm volatile("cp.async.wait_group 0;" ::: "memory");
        __syncthreads();
        if (i + 2 < NC) fill(i + 2);

        const uint4* sa = smu + (i % 3) * G_STAGE_U4;
        const uint4* sb = sa + 1024;
        #pragma unroll
        for (int ks = 0; ks < 4; ks++) {
            uint4 a0 = sa[ks*256 + (mtb + 0)*32 + lane];
            uint4 a1 = sa[ks*256 + (mtb + 1)*32 + lane];
            #pragma unroll
            for (int g = 0; g < 4; g++) {
                uint4 b4 = sb[ks*256 + (ngb2 + g)*32 + lane];
                mma_f16(acc[0][2*g  ], (const uint32_t*)&a0, b4.x, b4.y);
                mma_f16(acc[0][2*g+1], (const uint32_t*)&a0, b4.z, b4.w);
                mma_f16(acc[1][2*g  ], (const uint32_t*)&a1, b4.x, b4.y);
                mma_f16(acc[1][2*g+1], (const uint32_t*)&a1, b4.z, b4.w);
            }
        }
        __syncthreads();
    }

    if (MODE == 0) {
        float* C = (float*)Cv;
        #pragma unroll
        for (int mt2 = 0; mt2 < 2; mt2++) {
            const int r = mb*128 + (wid & 3)*32 + mt2*16 + grp;
            #pragma unroll
            for (int nt = 0; nt < 8; nt++) {
                const int c = ncol0 + (wid >> 2)*64 + nt*8 + 2*t4;
                const float bz0 = bias[c], bz1 = bias[c+1];
                *(float2*)&C[(size_t)r*N + c] =
                    make_float2(acc[mt2][nt][0] + bz0, acc[mt2][nt][1] + bz1);
                *(float2*)&C[(size_t)(r+8)*N + c] =
                    make_float2(acc[mt2][nt][2] + bz0, acc[mt2][nt][3] + bz1);
            }
        }
    } else {
        __half* C = (__half*)Cv;
        #pragma unroll
        for (int mt2 = 0; mt2 < 2; mt2++) {
            #pragma unroll
            for (int nt = 0; nt < 8; nt++) {
                const int cbase = (wid >> 2)*64 + nt*8 + 2*t4;
                #pragma unroll
                for (int e = 0; e < 4; e++) {
                    const int r = mb*128 + (wid & 3)*32 + mt2*16 + grp + ((e >= 2) ? 8 : 0);
                    const int c = cbase + (e & 1);
                    const __half val = __float2half_rn(acc[mt2][nt][e] + bias[c]);
                    const int tile = r >> 6;
                    const int rr = r & 63;
                    size_t off;
                    if (MODE == 1) {
                        // Kfh[tile][ks8][g4][lane]: key rows paired (w, w+8), feat k
                        const int g = rr >> 4, w = rr & 15;
                        const int ksf = c >> 4, cc = c & 15;
                        const int comp = (cc & 1) + ((cc >= 8) ? 2 : 0) + ((w >= 8) ? 4 : 0);
                        const int lane_f = (w & 7)*4 + ((cc & 7) >> 1);
                        off = (size_t)tile*8192 + ((size_t)ksf*128 + g*32 + lane_f)*8 + comp;
                    } else {
                        // Vfh[tile][ks4][g8][lane]: features paired (n, n+8), keys k
                        const int ksf = rr >> 4, w = rr & 15;
                        const int g = c >> 4, cc = c & 15;
                        const int comp = (w & 1) + ((w >= 8) ? 2 : 0) + ((cc >= 8) ? 4 : 0);
                        const int lane_f = (cc & 7)*4 + ((w & 7) >> 1);
                        off = (size_t)tile*8192 + ((size_t)ksf*256 + g*32 + lane_f)*8 + comp;
                    }
                    C[off] = val;
                }
            }
        }
    }
}

// Fused Q/K/V projection: blockIdx.x 0..15 = Q tiles, 16 = K (packed), 17 = V (packed)
__global__ __launch_bounds__(256)
void gemm_qkv(const float* __restrict__ bq, const float* __restrict__ bk,
              const float* __restrict__ bv)
{
    extern __shared__ char smraw[];
    const int KT = DD >> 6;   // 32
    const uint4* At = g_Xph + (size_t)blockIdx.y * KT * 1024;
    if (blockIdx.x < 16) {
        gemm_body<0>(At, g_WqPh + (size_t)blockIdx.x * KT * 1024,
                     bq, g_Q, DD, KT, blockIdx.y, blockIdx.x * 128, smraw);
    } else if (blockIdx.x == 16) {
        gemm_body<1>(At, g_WkvPh, bk, g_Kfh, HD, KT, blockIdx.y, 0, smraw);
    } else {
        gemm_body<2>(At, g_WkvPh + 32768, bv, g_Vfh, HD, KT, blockIdx.y, 0, smraw);
    }
}

// Output projection
__global__ __launch_bounds__(256)
void gemm_out(const float* __restrict__ bo, float* __restrict__ out)
{
    extern __shared__ char smraw[];
    const int KT = DD >> 6;
    gemm_body<0>(g_AOph + (size_t)blockIdx.y * KT * 1024,
                 g_WoPh + (size_t)blockIdx.x * KT * 1024,
                 bo, out, DD, KT, blockIdx.y, blockIdx.x * 128, smraw);
}

// ---------------- flash attention fp16: paired K/V tiles, packed-AO epilogue ----
// Stage = [Kf 1024 uint4][Vf 1024 uint4] = 32KB. 2 stages + Pw (half, stride 72).
#define FB_R 128
#define PS_STH 72
#define F_STAGE_U4 2048
#define PW_BYTE (2 * F_STAGE_U4 * 16)               // 65536
#define FLASH_SMEM (PW_BYTE + 8*16*PS_STH*2)        // 83968 B

__global__ __launch_bounds__(256)
void flash_f16(const float* __restrict__ Q, __half* __restrict__ AOp)
{
    extern __shared__ char smraw[];
    const uint32_t sb = s2u(smraw);

    const int tid  = threadIdx.x;
    const int lane = tid & 31;
    const int wid  = tid >> 5;
    const int grp  = lane >> 2;
    const int t4   = lane & 3;
    __half* Pw = (__half*)(smraw + PW_BYTE) + wid*16*PS_STH;

    const int qb = gridDim.x - 1 - blockIdx.x;   // longest blocks first
    const int h  = blockIdx.y;
    const int b  = blockIdx.z;
    const int q0 = qb * FB_R;
    const int qr = q0 + wid*16 + grp;

    const float scale = 0.08838834764831845f;

    // Q fragments (scaled, fp16) in registers: qf[ks8][4] regs
    const float* Qb = Q + (size_t)b*TT*DD + (size_t)h*HD;
    uint32_t qf[8][4];
    #pragma unroll
    for (int ks = 0; ks < 8; ks++) {
        const float* p = &Qb[(size_t)qr*DD + ks*16 + 2*t4];
        const float* p8 = p + (size_t)8*DD;
        qf[ks][0] = pk(p[0]*scale,  p[1]*scale);
        qf[ks][1] = pk(p8[0]*scale, p8[1]*scale);
        qf[ks][2] = pk(p[8]*scale,  p[9]*scale);
        qf[ks][3] = pk(p8[8]*scale, p8[9]*scale);
    }

    float of[16][4];
    #pragma unroll
    for (int nt = 0; nt < 16; nt++)
        #pragma unroll
        for (int e = 0; e < 4; e++) of[nt][e] = 0.f;

    float m_lo = -1e30f, m_hi = -1e30f, l_lo = 0.f, l_hi = 0.f;

    const uint4* Kt = g_Kfh + (size_t)b*(TT/64)*1024;
    const uint4* Vt = g_Vfh + (size_t)b*(TT/64)*1024;
    const int nkt = 2*(qb + 1);

    auto fill = [&](int t) {
        const uint32_t dst = sb + (uint32_t)(t & 1) * 32768;
        const uint4* sk = Kt + (size_t)t * 1024;
        const uint4* sv = Vt + (size_t)t * 1024;
        #pragma unroll
        for (int i = 0; i < 4; i++) {
            const int idx = tid + i*256;
            asm volatile("cp.async.cg.shared.global [%0], [%1], 16;"
                         :: "r"(dst + idx*16), "l"(sk + idx));
            asm volatile("cp.async.cg.shared.global [%0], [%1], 16;"
                         :: "r"(dst + 16384 + idx*16), "l"(sv + idx));
        }
        asm volatile("cp.async.commit_group;" ::: "memory");
    };

    fill(0);
    for (int kt = 0; kt < nkt; kt++) {
        if (kt + 1 < nkt) { fill(kt + 1); asm volatile("cp.async.wait_group 1;" ::: "memory"); }
        else              { asm volatile("cp.async.wait_group 0;" ::: "memory"); }
        __syncthreads();

        const uint4* Kf = (const uint4*)smraw + (size_t)(kt & 1) * F_STAGE_U4;
        const uint4* Vf = Kf + 1024;
        const int k0 = kt * 64;

        // ---- S = Q @ K^T ----
        float sacc[8][4];
        #pragma unroll
        for (int nt = 0; nt < 8; nt++)
            #pragma unroll
            for (int e = 0; e < 4; e++) sacc[nt][e] = 0.f;

        #pragma unroll
        for (int ks = 0; ks < 8; ks++) {
            #pragma unroll
            for (int g = 0; g < 4; g++) {
                uint4 b4 = Kf[ks*128 + g*32 + lane];
                mma_f16(sacc[2*g  ], qf[ks], b4.x, b4.y);
                mma_f16(sacc[2*g+1], qf[ks], b4.z, b4.w);
            }
        }

        // ---- causal mask ----
        if (kt >= nkt - 2) {
            #pragma unroll
            for (int nt = 0; nt < 8; nt++) {
                int kc = k0 + nt*8 + 2*t4;
                if (kc     > qr)     sacc[nt][0] = -1e30f;
                if (kc + 1 > qr)     sacc[nt][1] = -1e30f;
                if (kc     > qr + 8) sacc[nt][2] = -1e30f;
                if (kc + 1 > qr + 8) sacc[nt][3] = -1e30f;
            }
        }

        // ---- online softmax ----
        float mx_lo = -1e30f, mx_hi = -1e30f;
        #pragma unroll
        for (int nt = 0; nt < 8; nt++) {
            mx_lo = fmaxf(mx_lo, fmaxf(sacc[nt][0], sacc[nt][1]));
            mx_hi = fmaxf(mx_hi, fmaxf(sacc[nt][2], sacc[nt][3]));
        }
        mx_lo = fmaxf(mx_lo, __shfl_xor_sync(0xffffffffu, mx_lo, 1));
        mx_lo = fmaxf(mx_lo, __shfl_xor_sync(0xffffffffu, mx_lo, 2));
        mx_hi = fmaxf(mx_hi, __shfl_xor_sync(0xffffffffu, mx_hi, 1));
        mx_hi = fmaxf(mx_hi, __shfl_xor_sync(0xffffffffu, mx_hi, 2));

        const float mn_lo = fmaxf(m_lo, mx_lo);
        const float mn_hi = fmaxf(m_hi, mx_hi);
        const float corr_lo = __expf(m_lo - mn_lo);
        const float corr_hi = __expf(m_hi - mn_hi);

        float sum_lo = 0.f, sum_hi = 0.f;
        #pragma unroll
        for (int nt = 0; nt < 8; nt++) {
            sacc[nt][0] = __expf(sacc[nt][0] - mn_lo);
            sacc[nt][1] = __expf(sacc[nt][1] - mn_lo);
            sacc[nt][2] = __expf(sacc[nt][2] - mn_hi);
            sacc[nt][3] = __expf(sacc[nt][3] - mn_hi);
            sum_lo += sacc[nt][0] + sacc[nt][1];
            sum_hi += sacc[nt][2] + sacc[nt][3];
        }
        sum_lo += __shfl_xor_sync(0xffffffffu, sum_lo, 1);
        sum_lo += __shfl_xor_sync(0xffffffffu, sum_lo, 2);
        sum_hi += __shfl_xor_sync(0xffffffffu, sum_hi, 1);
        sum_hi += __shfl_xor_sync(0xffffffffu, sum_hi, 2);

        l_lo = l_lo * corr_lo + sum_lo;  m_lo = mn_lo;
        l_hi = l_hi * corr_hi + sum_hi;  m_hi = mn_hi;

        #pragma unroll
        for (int nt = 0; nt < 16; nt++) {
            of[nt][0] *= corr_lo;  of[nt][1] *= corr_lo;
            of[nt][2] *= corr_hi;  of[nt][3] *= corr_hi;
        }

        // ---- P -> per-warp smem as fp16 (C-layout -> A-layout) ----
        #pragma unroll
        for (int nt = 0; nt < 8; nt++) {
            *(uint32_t*)&Pw[grp*PS_STH + nt*8 + 2*t4]       = pk(sacc[nt][0], sacc[nt][1]);
            *(uint32_t*)&Pw[(grp + 8)*PS_STH + nt*8 + 2*t4] = pk(sacc[nt][2], sacc[nt][3]);
        }
        __syncwarp();

        // ---- O += P @ V ----
        #pragma unroll
        for (int ks = 0; ks < 4; ks++) {
            uint32_t pf[4];
            pf[0] = *(const uint32_t*)&Pw[grp*PS_STH       + ks*16 + 2*t4];
            pf[1] = *(const uint32_t*)&Pw[(grp + 8)*PS_STH + ks*16 + 2*t4];
            pf[2] = *(const uint32_t*)&Pw[grp*PS_STH       + ks*16 + 2*t4 + 8];
            pf[3] = *(const uint32_t*)&Pw[(grp + 8)*PS_STH + ks*16 + 2*t4 + 8];
            #pragma unroll
            for (int g = 0; g < 8; g++) {
                uint4 b4 = Vf[ks*256 + g*32 + lane];
                mma_f16(of[2*g  ], pf, b4.x, b4.y);
                mma_f16(of[2*g+1], pf, b4.z, b4.w);
            }
        }
        __syncthreads();   // stage reads done before next fill overwrites
    }

    // ---- normalize, write fp16 DIRECTLY in packed A-fragment order ----
    const float inv_lo = 1.f / l_lo;
    const float inv_hi = 1.f / l_hi;
    #pragma unroll
    for (int nt = 0; nt < 16; nt++) {
        #pragma unroll
        for (int e = 0; e < 4; e++) {
            const int m = b*TT + qr + ((e >= 2) ? 8 : 0);
            const int k = h*HD + nt*8 + 2*t4 + (e & 1);
            const float val = of[nt][e] * ((e < 2) ? inv_lo : inv_hi);
            const int tile = (m >> 7)*32 + (k >> 6);
            const int ksf = (k >> 4) & 3;
            const int mt = (m >> 4) & 7;
            const int w = m & 15;                 // = grp or grp+8
            const int cc = k & 15;
            const int comp = (cc & 1) + ((w >= 8) ? 2 : 0) + ((cc >= 8) ? 4 : 0);
            const int lane_f = (w & 7)*4 + ((cc & 7) >> 1);
            const size_t off = (size_t)tile*8192 + ((size_t)ksf*256 + mt*32 + lane_f)*8 + comp;
            AOp[off] = __float2half_rn(val);
        }
    }
}

// ---------------- launch ----------------
extern "C" void kernel_launch(void* const* d_in, const int* in_sizes, int n_in,
                              void* d_out, int out_size)
{
    const float* x  = (const float*)d_in[0];
    const float* Wq = (const float*)d_in[1];
    const float* bq = (const float*)d_in[2];
    const float* Wk = (const float*)d_in[3];
    const float* bk = (const float*)d_in[4];
    const float* Wv = (const float*)d_in[5];
    const float* bv = (const float*)d_in[6];
    const float* Wo = (const float*)d_in[7];
    const float* bo = (const float*)d_in[8];
    float* out = (float*)d_out;

    float* Qp;
    __half* AOph;
    cudaGetSymbolAddress((void**)&Qp, g_Q);
    { void* t; cudaGetSymbolAddress(&t, g_AOph); AOph = (__half*)t; }

    cudaFuncSetAttribute(gemm_qkv, cudaFuncAttributeMaxDynamicSharedMemorySize, G_SMEM);
    cudaFuncSetAttribute(gemm_out, cudaFuncAttributeMaxDynamicSharedMemorySize, G_SMEM);
    cudaFuncSetAttribute(flash_f16, cudaFuncAttributeMaxDynamicSharedMemorySize, FLASH_SMEM);

    // ---- pack all operands (fp16, fragment order) in one launch ----
    pack_all<<<PACK_BLOCKS, 256>>>(x, Wq, Wk, Wv, Wo);

    // ---- fused Q/K/V projections (K/V write fp16 fragment tiles directly) ----
    gemm_qkv<<<dim3(18, MROWS/128), 256, G_SMEM>>>(bq, bk, bv);

    // ---- attention (writes packed fp16 AO directly) ----
    flash_f16<<<dim3(TT/FB_R, HH, BB), 256, FLASH_SMEM>>>(Qp, AOph);

    // ---- output projection ----
    gemm_out<<<dim3(DD/128, MROWS/128), 256, G_SMEM>>>(bo, out);
}